// round 8
// baseline (speedup 1.0000x reference)
#include <cuda_runtime.h>
#include <cuda_bf16.h>

#define N_NODES   100000
#define N_EDGES_MAX 1600000
#define N_GRAPHS  256
#define IN_DIM    205
#define HID_DIM   128
#define FC_DIM    64
#define OUT_DIM   2
#define SCAN_BLK  1024

typedef unsigned long long ull;

// ---------------- scratch (static device globals; referenced ONLY from device code) ----------------
__device__ __align__(128) float g_h1[(size_t)N_NODES * HID_DIM];   // layer-1 GEMM output H1
__device__ __align__(128) float g_h2[(size_t)N_NODES * HID_DIM];   // layer-2 GEMM output H2
__device__ __align__(128) float g_agg[(size_t)N_NODES * HID_DIM];  // layer-1 aggregate (pre-bias)
__device__ int   g_degi[N_NODES];
__device__ int   g_rowstart[N_NODES];
__device__ int   g_cursor[N_NODES];
__device__ int   g_blocksum[128];
__device__ int   g_csrc[N_EDGES_MAX];
__device__ float g_ds[N_NODES];
__device__ float g_gsum[N_GRAPHS * HID_DIM];
__device__ float g_gcnt[N_GRAPHS];

// ---------------- f32x2 packed helpers ----------------
__device__ __forceinline__ ull pk2(float a) {
    ull r; asm("mov.b64 %0, {%1, %1};" : "=l"(r) : "f"(a)); return r;
}
__device__ __forceinline__ void fma2(ull& d, ull a, ull b) {
    asm("fma.rn.f32x2 %0, %1, %2, %0;" : "+l"(d) : "l"(a), "l"(b));
}

// ---------------- zero the small accumulators ----------------
__global__ void zero_kernel() {
    int i = blockIdx.x * blockDim.x + threadIdx.x;
    if (i < N_NODES) g_degi[i] = 0;
    if (i < N_GRAPHS * HID_DIM) g_gsum[i] = 0.0f;
}

// ---------------- in-degree histogram ----------------
__global__ void hist_kernel(const int* __restrict__ dst, int E) {
    int e = blockIdx.x * blockDim.x + threadIdx.x;
    if (e < E) atomicAdd(&g_degi[dst[e]], 1);
}

// ---------------- scan level 1: per-block exclusive scan + block sums ----------------
__global__ void scan1_kernel() {
    __shared__ int sh[SCAN_BLK];
    int i = blockIdx.x * SCAN_BLK + threadIdx.x;
    int v = (i < N_NODES) ? g_degi[i] : 0;
    sh[threadIdx.x] = v;
    __syncthreads();
    for (int off = 1; off < SCAN_BLK; off <<= 1) {
        int t = (threadIdx.x >= off) ? sh[threadIdx.x - off] : 0;
        __syncthreads();
        sh[threadIdx.x] += t;
        __syncthreads();
    }
    if (i < N_NODES) g_rowstart[i] = sh[threadIdx.x] - v;  // exclusive
    if (threadIdx.x == SCAN_BLK - 1) g_blocksum[blockIdx.x] = sh[threadIdx.x];
}

// -------- scan level 2 fused: parallel block-sum prefix; NO atomics --------
__global__ void scan3_kernel(int nb) {
    __shared__ int pref[256];
    int t = threadIdx.x;
    int v = (t < nb) ? g_blocksum[t] : 0;
    pref[t] = v;
    __syncthreads();
    for (int off = 1; off < 256; off <<= 1) {
        int u = (t >= off) ? pref[t - off] : 0;
        __syncthreads();
        pref[t] += u;
        __syncthreads();
    }
    int ex = pref[t] - v;   // exclusive
    __syncthreads();
    pref[t] = ex;
    __syncthreads();

    int i = blockIdx.x * blockDim.x + t;
    if (i >= N_NODES) return;
    int rs = g_rowstart[i] + pref[i / SCAN_BLK];
    g_rowstart[i] = rs;
    g_cursor[i] = rs;
    g_ds[i] = rsqrtf((float)g_degi[i] + 1.0f);
}

// ---------------- graph node counts via binary search on SORTED batch ----------------
__global__ void gcnt_kernel(const int* __restrict__ batch, int n) {
    __shared__ int lb[N_GRAPHS + 1];
    int g = threadIdx.x;
    int lo = 0, hi = n;
    while (lo < hi) {                      // first i with batch[i] >= g
        int mid = (lo + hi) >> 1;
        if (batch[mid] < g) lo = mid + 1; else hi = mid;
    }
    lb[g] = lo;
    if (g == 0) lb[N_GRAPHS] = n;
    __syncthreads();
    g_gcnt[g] = (float)(lb[g + 1] - lb[g]);
}

// ---------------- CSR scatter (bucket order irrelevant: sum is commutative) ----------------
__global__ void scatter_kernel(const int* __restrict__ src, const int* __restrict__ dst, int E) {
    int e = blockIdx.x * blockDim.x + threadIdx.x;
    if (e < E) {
        int pos = atomicAdd(&g_cursor[dst[e]], 1);
        g_csrc[pos] = src[e];
    }
}

// ---------------- GEMM (f32x2 packed): OUT = in @ W ----------------
// PRE=false: in = X (global), OUT = g_h1.   PRE=true: in = relu(g_agg + bias), OUT = g_h2.
// Block: 32 rows x 128 cols, 128 threads, thread tile 4 rows x 8 cols (16 f32x2 accs).
// W pairs loaded pre-packed via ulonglong2 (contiguous floats ARE the f32x2 lanes).
template <int K, bool PRE>
__global__ void __launch_bounds__(128) gemm_kernel(const float* __restrict__ X,
                                                   const float* __restrict__ W,
                                                   const float* __restrict__ bias,
                                                   int N) {
    constexpr int KP = (K + 3) & ~3;
    constexpr int K4 = K & ~3;
    __shared__ float xs[32 * KP];   // 26624B (K=205) or 16384B (K=128)
    float* OUT = PRE ? g_h2 : g_h1;
    const float* in = PRE ? g_agg : X;
    int row0 = blockIdx.x * 32;
    int tid = threadIdx.x;

    for (int idx = tid; idx < 32 * K; idx += 128) {
        int m = idx / K;
        int k = idx - m * K;
        int row = row0 + m;
        float v = (row < N) ? in[(size_t)row * K + k] : 0.0f;
        if (PRE) v = fmaxf(v + bias[k], 0.0f);
        xs[m * KP + k] = v;
    }
    __syncthreads();

    int f0 = (tid & 15) * 8;     // 8 output columns
    int m0 = (tid >> 4) * 4;     // 4 output rows

    ull acc[4][4];
#pragma unroll
    for (int m = 0; m < 4; m++)
#pragma unroll
        for (int j = 0; j < 4; j++) acc[m][j] = 0ull;

    const float4* xs4 = reinterpret_cast<const float4*>(xs);

    for (int k = 0; k < K4; k += 4) {
        ull w[4][4];
#pragma unroll
        for (int kk = 0; kk < 4; kk++) {
            const ulonglong2* wp = reinterpret_cast<const ulonglong2*>(&W[(k + kk) * HID_DIM + f0]);
            ulonglong2 wlo = wp[0];
            ulonglong2 whi = wp[1];
            w[kk][0] = wlo.x; w[kk][1] = wlo.y; w[kk][2] = whi.x; w[kk][3] = whi.y;
        }
#pragma unroll
        for (int m = 0; m < 4; m++) {
            float4 xv = xs4[((m0 + m) * KP + k) >> 2];
            ull d0 = pk2(xv.x);
            fma2(acc[m][0], d0, w[0][0]); fma2(acc[m][1], d0, w[0][1]);
            fma2(acc[m][2], d0, w[0][2]); fma2(acc[m][3], d0, w[0][3]);
            ull d1 = pk2(xv.y);
            fma2(acc[m][0], d1, w[1][0]); fma2(acc[m][1], d1, w[1][1]);
            fma2(acc[m][2], d1, w[1][2]); fma2(acc[m][3], d1, w[1][3]);
            ull d2 = pk2(xv.z);
            fma2(acc[m][0], d2, w[2][0]); fma2(acc[m][1], d2, w[2][1]);
            fma2(acc[m][2], d2, w[2][2]); fma2(acc[m][3], d2, w[2][3]);
            ull d3 = pk2(xv.w);
            fma2(acc[m][0], d3, w[3][0]); fma2(acc[m][1], d3, w[3][1]);
            fma2(acc[m][2], d3, w[3][2]); fma2(acc[m][3], d3, w[3][3]);
        }
    }
    // K tail (K=205 -> one scalar k)
    for (int k = K4; k < K; k++) {
        const ulonglong2* wp = reinterpret_cast<const ulonglong2*>(&W[k * HID_DIM + f0]);
        ulonglong2 wlo = wp[0];
        ulonglong2 whi = wp[1];
#pragma unroll
        for (int m = 0; m < 4; m++) {
            ull d = pk2(xs[(m0 + m) * KP + k]);
            fma2(acc[m][0], d, wlo.x); fma2(acc[m][1], d, wlo.y);
            fma2(acc[m][2], d, whi.x); fma2(acc[m][3], d, whi.y);
        }
    }

#pragma unroll
    for (int m = 0; m < 4; m++) {
        int row = row0 + m0 + m;
        if (row < N) {
            ulonglong2* orow = reinterpret_cast<ulonglong2*>(&OUT[(size_t)row * HID_DIM + f0]);
            ulonglong2 a, b;
            a.x = acc[m][0]; a.y = acc[m][1];
            b.x = acc[m][2]; b.y = acc[m][3];
            orow[0] = a;
            orow[1] = b;
        }
    }
}

// ------- CSR aggregation: one warp per dst node; lane owns a float4 -------
// FINAL=false: g_agg[d] = ds[d]*(sum ds[s]*H1[s] + ds[d]*H1[d])        (pre-bias)
// FINAL=true : relu(same over H2 + b2) -> RED into g_gsum[batch[d]]
template <bool FINAL>
__global__ void __launch_bounds__(256) agg_kernel(const int* __restrict__ batch,
                                                  const float* __restrict__ b2,
                                                  int n) {
    int node = (blockIdx.x * blockDim.x + threadIdx.x) >> 5;
    int lane = threadIdx.x & 31;
    if (node >= n) return;

    const float4* __restrict__ hs = reinterpret_cast<const float4*>(FINAL ? g_h2 : g_h1);
    float dsd = g_ds[node];
    float4 self = hs[(size_t)node * 32 + lane];
    float4 sum = make_float4(dsd * self.x, dsd * self.y, dsd * self.z, dsd * self.w);

    int start = g_rowstart[node];
    int deg = g_degi[node];

    for (int j0 = 0; j0 < deg; j0 += 32) {
        int idx = j0 + lane;
        int myid = (idx < deg) ? g_csrc[start + idx] : 0;
        float myds = g_ds[myid];
        int cnt = min(32, deg - j0);
#pragma unroll 4
        for (int k = 0; k < cnt; k++) {
            int s = __shfl_sync(0xffffffffu, myid, k);
            float dss = __shfl_sync(0xffffffffu, myds, k);
            float4 v = hs[(size_t)s * 32 + lane];
            sum.x = fmaf(dss, v.x, sum.x);
            sum.y = fmaf(dss, v.y, sum.y);
            sum.z = fmaf(dss, v.z, sum.z);
            sum.w = fmaf(dss, v.w, sum.w);
        }
    }

    if (!FINAL) {
        reinterpret_cast<float4*>(g_agg)[(size_t)node * 32 + lane] =
            make_float4(sum.x * dsd, sum.y * dsd, sum.z * dsd, sum.w * dsd);
    } else {
        float4 bv = reinterpret_cast<const float4*>(b2)[lane];
        float vx = fmaxf(fmaf(sum.x, dsd, bv.x), 0.0f);
        float vy = fmaxf(fmaf(sum.y, dsd, bv.y), 0.0f);
        float vz = fmaxf(fmaf(sum.z, dsd, bv.z), 0.0f);
        float vw = fmaxf(fmaf(sum.w, dsd, bv.w), 0.0f);
        float4* out = reinterpret_cast<float4*>(g_gsum) + batch[node] * 32 + lane;
        asm volatile("red.global.add.v4.f32 [%0], {%1, %2, %3, %4};"
                     :: "l"(out), "f"(vx), "f"(vy), "f"(vz), "f"(vw)
                     : "memory");
    }
}

// ---------------- FC head ----------------
__global__ void __launch_bounds__(64) fc_kernel(const float* __restrict__ Wf1,
                                                const float* __restrict__ bf1,
                                                const float* __restrict__ Wf2,
                                                const float* __restrict__ bf2,
                                                float* __restrict__ out) {
    __shared__ float grow[HID_DIM];
    __shared__ float a[FC_DIM];
    int g = blockIdx.x;
    int t = threadIdx.x;
    float inv = 1.0f / fmaxf(g_gcnt[g], 1.0f);
    grow[t] = g_gsum[g * HID_DIM + t] * inv;
    grow[t + 64] = g_gsum[g * HID_DIM + 64 + t] * inv;
    __syncthreads();
    float acc = bf1[t];
#pragma unroll 8
    for (int k = 0; k < HID_DIM; k++) acc += grow[k] * Wf1[k * FC_DIM + t];
    a[t] = fmaxf(acc, 0.0f);
    __syncthreads();
    if (t < OUT_DIM) {
        float o = bf2[t];
#pragma unroll 8
        for (int j = 0; j < FC_DIM; j++) o += a[j] * Wf2[j * OUT_DIM + t];
        out[g * OUT_DIM + t] = o;
    }
}

// ---------------- fork/join resources ----------------
struct SideStream {
    cudaStream_t s = nullptr;
    cudaEvent_t fork = nullptr, join = nullptr;
    SideStream() {
        if (cudaStreamCreateWithFlags(&s, cudaStreamNonBlocking) != cudaSuccess) { s = nullptr; return; }
        if (cudaEventCreateWithFlags(&fork, cudaEventDisableTiming) != cudaSuccess) { s = nullptr; return; }
        if (cudaEventCreateWithFlags(&join, cudaEventDisableTiming) != cudaSuccess) { s = nullptr; return; }
    }
};
static SideStream& side() { static SideStream ss; return ss; }

// ---------------- launcher ----------------
extern "C" void kernel_launch(void* const* d_in, const int* in_sizes, int n_in,
                              void* d_out, int out_size) {
    const float* x   = (const float*)d_in[0];
    const int* ei    = (const int*)d_in[1];   // [2, E] int32
    const int* batch = (const int*)d_in[2];
    const float* W1  = (const float*)d_in[3];
    const float* b1  = (const float*)d_in[4];
    const float* W2  = (const float*)d_in[5];
    const float* b2  = (const float*)d_in[6];
    const float* Wf1 = (const float*)d_in[7];
    const float* bf1 = (const float*)d_in[8];
    const float* Wf2 = (const float*)d_in[9];
    const float* bf2 = (const float*)d_in[10];
    float* out = (float*)d_out;

    int E = in_sizes[1] / 2;
    int N = in_sizes[2];
    const int* src = ei;
    const int* dst = ei + E;
    int nb = (N_NODES + SCAN_BLK - 1) / SCAN_BLK;

    SideStream& ss = side();
    bool forked = (ss.s != nullptr);
    cudaStream_t cs = forked ? ss.s : (cudaStream_t)0;

    if (forked) {
        cudaEventRecord(ss.fork, 0);
        cudaStreamWaitEvent(ss.s, ss.fork, 0);
    }

    // --- CSR build chain (side stream): independent of GEMM1 ---
    zero_kernel<<<(N_NODES + 255) / 256, 256, 0, cs>>>();
    hist_kernel<<<(E + 255) / 256, 256, 0, cs>>>(dst, E);
    scan1_kernel<<<nb, SCAN_BLK, 0, cs>>>();
    scan3_kernel<<<(N_NODES + 255) / 256, 256, 0, cs>>>(nb);
    scatter_kernel<<<(E + 255) / 256, 256, 0, cs>>>(src, dst, E);
    gcnt_kernel<<<1, N_GRAPHS, 0, cs>>>(batch, N);
    if (forked) cudaEventRecord(ss.join, ss.s);

    // --- GEMM1 -> g_h1 (no ds dependency) ---
    gemm_kernel<IN_DIM, false><<<(N + 31) / 32, 128>>>(x, W1, nullptr, N);

    if (forked) cudaStreamWaitEvent(0, ss.join, 0);

    // --- layer-1 aggregation -> g_agg ---
    int agg_blocks = (int)(((long long)N * 32 + 255) / 256);
    agg_kernel<false><<<agg_blocks, 256>>>(batch, b2, N);

    // --- GEMM2 (relu(g_agg + b1) on load) -> g_h2 ---
    gemm_kernel<HID_DIM, true><<<(N + 31) / 32, 128>>>(nullptr, W2, b1, N);

    // --- layer-2 aggregation + bias + relu + mean-pool accumulate ---
    agg_kernel<true><<<agg_blocks, 256>>>(batch, b2, N);

    fc_kernel<<<N_GRAPHS, 64>>>(Wf1, bf1, Wf2, bf2, out);
}

// round 9
// speedup vs baseline: 1.2177x; 1.2177x over previous
#include <cuda_runtime.h>
#include <cuda_bf16.h>

#define N_NODES   100000
#define N_EDGES_MAX 1600000
#define N_GRAPHS  256
#define IN_DIM    205
#define HID_DIM   128
#define FC_DIM    64
#define OUT_DIM   2
#define SCAN_BLK  1024

// ---------------- scratch (static device globals; referenced ONLY from device code) ----------------
__device__ __align__(128) float g_h1[(size_t)N_NODES * HID_DIM];   // layer-1 GEMM output H1
__device__ __align__(128) float g_h2[(size_t)N_NODES * HID_DIM];   // layer-2 GEMM output H2
__device__ __align__(128) float g_agg[(size_t)N_NODES * HID_DIM];  // layer-1 aggregate (pre-bias)
__device__ int   g_degi[N_NODES];
__device__ int   g_rowstart[N_NODES];
__device__ int   g_cursor[N_NODES];
__device__ int   g_blocksum[128];
__device__ int   g_csrc[N_EDGES_MAX];
__device__ float g_ds[N_NODES];
__device__ float g_gsum[N_GRAPHS * HID_DIM];
__device__ float g_gcnt[N_GRAPHS];

// ---------------- zero the small accumulators ----------------
__global__ void zero_kernel() {
    int i = blockIdx.x * blockDim.x + threadIdx.x;
    if (i < N_NODES) g_degi[i] = 0;
    if (i < N_GRAPHS * HID_DIM) g_gsum[i] = 0.0f;
}

// ---------------- in-degree histogram ----------------
__global__ void hist_kernel(const int* __restrict__ dst, int E) {
    int e = blockIdx.x * blockDim.x + threadIdx.x;
    if (e < E) atomicAdd(&g_degi[dst[e]], 1);
}

// ---------------- scan level 1: per-block exclusive scan + block sums ----------------
__global__ void scan1_kernel() {
    __shared__ int sh[SCAN_BLK];
    int i = blockIdx.x * SCAN_BLK + threadIdx.x;
    int v = (i < N_NODES) ? g_degi[i] : 0;
    sh[threadIdx.x] = v;
    __syncthreads();
    for (int off = 1; off < SCAN_BLK; off <<= 1) {
        int t = (threadIdx.x >= off) ? sh[threadIdx.x - off] : 0;
        __syncthreads();
        sh[threadIdx.x] += t;
        __syncthreads();
    }
    if (i < N_NODES) g_rowstart[i] = sh[threadIdx.x] - v;  // exclusive
    if (threadIdx.x == SCAN_BLK - 1) g_blocksum[blockIdx.x] = sh[threadIdx.x];
}

// -------- scan level 2 fused: parallel block-sum prefix; NO atomics --------
__global__ void scan3_kernel(int nb) {
    __shared__ int pref[256];
    int t = threadIdx.x;
    int v = (t < nb) ? g_blocksum[t] : 0;
    pref[t] = v;
    __syncthreads();
    for (int off = 1; off < 256; off <<= 1) {
        int u = (t >= off) ? pref[t - off] : 0;
        __syncthreads();
        pref[t] += u;
        __syncthreads();
    }
    int ex = pref[t] - v;   // exclusive
    __syncthreads();
    pref[t] = ex;
    __syncthreads();

    int i = blockIdx.x * blockDim.x + t;
    if (i >= N_NODES) return;
    int rs = g_rowstart[i] + pref[i / SCAN_BLK];
    g_rowstart[i] = rs;
    g_cursor[i] = rs;
    g_ds[i] = rsqrtf((float)g_degi[i] + 1.0f);
}

// ---------------- graph node counts via binary search on SORTED batch ----------------
__global__ void gcnt_kernel(const int* __restrict__ batch, int n) {
    __shared__ int lb[N_GRAPHS + 1];
    int g = threadIdx.x;
    int lo = 0, hi = n;
    while (lo < hi) {                      // first i with batch[i] >= g
        int mid = (lo + hi) >> 1;
        if (batch[mid] < g) lo = mid + 1; else hi = mid;
    }
    lb[g] = lo;
    if (g == 0) lb[N_GRAPHS] = n;
    __syncthreads();
    g_gcnt[g] = (float)(lb[g + 1] - lb[g]);
}

// ---------------- CSR scatter (bucket order irrelevant: sum is commutative) ----------------
__global__ void scatter_kernel(const int* __restrict__ src, const int* __restrict__ dst, int E) {
    int e = blockIdx.x * blockDim.x + threadIdx.x;
    if (e < E) {
        int pos = atomicAdd(&g_cursor[dst[e]], 1);
        g_csrc[pos] = src[e];
    }
}

// ---------------- GEMM (scalar FFMA, proven fastest): OUT = in @ W ----------------
// PRE=false: in = X (global), OUT = g_h1.   PRE=true: in = relu(g_agg + bias), OUT = g_h2.
// Block: 32 rows x 128 cols, 128 threads, each thread 8 rows x 4 cols, k-quad float4 LDS.
template <int K, bool PRE>
__global__ void __launch_bounds__(128) gemm_kernel(const float* __restrict__ X,
                                                   const float* __restrict__ W,
                                                   const float* __restrict__ bias,
                                                   int N) {
    constexpr int KP = (K + 3) & ~3;
    constexpr int K4 = K & ~3;
    __shared__ float xs[32 * KP];   // 26624B (K=205) or 16384B (K=128)
    float* OUT = PRE ? g_h2 : g_h1;
    const float* in = PRE ? g_agg : X;
    int row0 = blockIdx.x * 32;
    int tid = threadIdx.x;

    for (int idx = tid; idx < 32 * K; idx += 128) {
        int m = idx / K;
        int k = idx - m * K;
        int row = row0 + m;
        float v = (row < N) ? in[(size_t)row * K + k] : 0.0f;
        if (PRE) v = fmaxf(v + bias[k], 0.0f);
        xs[m * KP + k] = v;
    }
    __syncthreads();

    int f0 = (tid & 31) * 4;
    int m0 = (tid >> 5) * 8;

    float acc[8][4];
#pragma unroll
    for (int m = 0; m < 8; m++)
#pragma unroll
        for (int j = 0; j < 4; j++) acc[m][j] = 0.0f;

    const float4* xs4 = reinterpret_cast<const float4*>(xs);

    for (int k = 0; k < K4; k += 4) {
        float4 w0 = *reinterpret_cast<const float4*>(&W[(k + 0) * HID_DIM + f0]);
        float4 w1 = *reinterpret_cast<const float4*>(&W[(k + 1) * HID_DIM + f0]);
        float4 w2 = *reinterpret_cast<const float4*>(&W[(k + 2) * HID_DIM + f0]);
        float4 w3 = *reinterpret_cast<const float4*>(&W[(k + 3) * HID_DIM + f0]);
#pragma unroll
        for (int m = 0; m < 8; m++) {
            float4 xv = xs4[((m0 + m) * KP + k) >> 2];
            acc[m][0] = fmaf(xv.x, w0.x, fmaf(xv.y, w1.x, fmaf(xv.z, w2.x, fmaf(xv.w, w3.x, acc[m][0]))));
            acc[m][1] = fmaf(xv.x, w0.y, fmaf(xv.y, w1.y, fmaf(xv.z, w2.y, fmaf(xv.w, w3.y, acc[m][1]))));
            acc[m][2] = fmaf(xv.x, w0.z, fmaf(xv.y, w1.z, fmaf(xv.z, w2.z, fmaf(xv.w, w3.z, acc[m][2]))));
            acc[m][3] = fmaf(xv.x, w0.w, fmaf(xv.y, w1.w, fmaf(xv.z, w2.w, fmaf(xv.w, w3.w, acc[m][3]))));
        }
    }
    for (int k = K4; k < K; k++) {
        float4 w = *reinterpret_cast<const float4*>(&W[k * HID_DIM + f0]);
#pragma unroll
        for (int m = 0; m < 8; m++) {
            float xv = xs[(m0 + m) * KP + k];
            acc[m][0] = fmaf(xv, w.x, acc[m][0]);
            acc[m][1] = fmaf(xv, w.y, acc[m][1]);
            acc[m][2] = fmaf(xv, w.z, acc[m][2]);
            acc[m][3] = fmaf(xv, w.w, acc[m][3]);
        }
    }

#pragma unroll
    for (int m = 0; m < 8; m++) {
        int row = row0 + m0 + m;
        if (row < N) {
            *reinterpret_cast<float4*>(&OUT[(size_t)row * HID_DIM + f0]) =
                make_float4(acc[m][0], acc[m][1], acc[m][2], acc[m][3]);
        }
    }
}

// ------- CSR aggregation: one warp per dst node; lane owns a float4 -------
// FINAL=false: g_agg[d] = ds[d]*(sum ds[s]*H1[s] + ds[d]*H1[d])        (pre-bias)
// FINAL=true : relu(same over H2 + b2) -> RED into g_gsum[batch[d]]
template <bool FINAL>
__global__ void __launch_bounds__(256) agg_kernel(const int* __restrict__ batch,
                                                  const float* __restrict__ b2,
                                                  int n) {
    int node = (blockIdx.x * blockDim.x + threadIdx.x) >> 5;
    int lane = threadIdx.x & 31;
    if (node >= n) return;

    const float4* __restrict__ hs = reinterpret_cast<const float4*>(FINAL ? g_h2 : g_h1);
    float dsd = g_ds[node];
    float4 self = hs[(size_t)node * 32 + lane];
    float4 sum = make_float4(dsd * self.x, dsd * self.y, dsd * self.z, dsd * self.w);

    int start = g_rowstart[node];
    int deg = g_degi[node];

    for (int j0 = 0; j0 < deg; j0 += 32) {
        int idx = j0 + lane;
        int myid = (idx < deg) ? g_csrc[start + idx] : 0;
        float myds = g_ds[myid];
        int cnt = min(32, deg - j0);
#pragma unroll 4
        for (int k = 0; k < cnt; k++) {
            int s = __shfl_sync(0xffffffffu, myid, k);
            float dss = __shfl_sync(0xffffffffu, myds, k);
            float4 v = hs[(size_t)s * 32 + lane];
            sum.x = fmaf(dss, v.x, sum.x);
            sum.y = fmaf(dss, v.y, sum.y);
            sum.z = fmaf(dss, v.z, sum.z);
            sum.w = fmaf(dss, v.w, sum.w);
        }
    }

    if (!FINAL) {
        reinterpret_cast<float4*>(g_agg)[(size_t)node * 32 + lane] =
            make_float4(sum.x * dsd, sum.y * dsd, sum.z * dsd, sum.w * dsd);
    } else {
        float4 bv = reinterpret_cast<const float4*>(b2)[lane];
        float vx = fmaxf(fmaf(sum.x, dsd, bv.x), 0.0f);
        float vy = fmaxf(fmaf(sum.y, dsd, bv.y), 0.0f);
        float vz = fmaxf(fmaf(sum.z, dsd, bv.z), 0.0f);
        float vw = fmaxf(fmaf(sum.w, dsd, bv.w), 0.0f);
        float4* out = reinterpret_cast<float4*>(g_gsum) + batch[node] * 32 + lane;
        asm volatile("red.global.add.v4.f32 [%0], {%1, %2, %3, %4};"
                     :: "l"(out), "f"(vx), "f"(vy), "f"(vz), "f"(vw)
                     : "memory");
    }
}

// ---------------- FC head ----------------
__global__ void __launch_bounds__(64) fc_kernel(const float* __restrict__ Wf1,
                                                const float* __restrict__ bf1,
                                                const float* __restrict__ Wf2,
                                                const float* __restrict__ bf2,
                                                float* __restrict__ out) {
    __shared__ float grow[HID_DIM];
    __shared__ float a[FC_DIM];
    int g = blockIdx.x;
    int t = threadIdx.x;
    float inv = 1.0f / fmaxf(g_gcnt[g], 1.0f);
    grow[t] = g_gsum[g * HID_DIM + t] * inv;
    grow[t + 64] = g_gsum[g * HID_DIM + 64 + t] * inv;
    __syncthreads();
    float acc = bf1[t];
#pragma unroll 8
    for (int k = 0; k < HID_DIM; k++) acc += grow[k] * Wf1[k * FC_DIM + t];
    a[t] = fmaxf(acc, 0.0f);
    __syncthreads();
    if (t < OUT_DIM) {
        float o = bf2[t];
#pragma unroll 8
        for (int j = 0; j < FC_DIM; j++) o += a[j] * Wf2[j * OUT_DIM + t];
        out[g * OUT_DIM + t] = o;
    }
}

// ---------------- fork/join resources ----------------
struct SideStream {
    cudaStream_t s = nullptr;
    cudaEvent_t fork = nullptr, join = nullptr;
    SideStream() {
        if (cudaStreamCreateWithFlags(&s, cudaStreamNonBlocking) != cudaSuccess) { s = nullptr; return; }
        if (cudaEventCreateWithFlags(&fork, cudaEventDisableTiming) != cudaSuccess) { s = nullptr; return; }
        if (cudaEventCreateWithFlags(&join, cudaEventDisableTiming) != cudaSuccess) { s = nullptr; return; }
    }
};
static SideStream& side() { static SideStream ss; return ss; }

// ---------------- launcher ----------------
extern "C" void kernel_launch(void* const* d_in, const int* in_sizes, int n_in,
                              void* d_out, int out_size) {
    const float* x   = (const float*)d_in[0];
    const int* ei    = (const int*)d_in[1];   // [2, E] int32
    const int* batch = (const int*)d_in[2];
    const float* W1  = (const float*)d_in[3];
    const float* b1  = (const float*)d_in[4];
    const float* W2  = (const float*)d_in[5];
    const float* b2  = (const float*)d_in[6];
    const float* Wf1 = (const float*)d_in[7];
    const float* bf1 = (const float*)d_in[8];
    const float* Wf2 = (const float*)d_in[9];
    const float* bf2 = (const float*)d_in[10];
    float* out = (float*)d_out;

    int E = in_sizes[1] / 2;
    int N = in_sizes[2];
    const int* src = ei;
    const int* dst = ei + E;
    int nb = (N_NODES + SCAN_BLK - 1) / SCAN_BLK;

    SideStream& ss = side();
    bool forked = (ss.s != nullptr);
    cudaStream_t cs = forked ? ss.s : (cudaStream_t)0;

    if (forked) {
        cudaEventRecord(ss.fork, 0);
        cudaStreamWaitEvent(ss.s, ss.fork, 0);
    }

    // --- CSR build chain (side stream): independent of GEMM1 ---
    zero_kernel<<<(N_NODES + 255) / 256, 256, 0, cs>>>();
    hist_kernel<<<(E + 255) / 256, 256, 0, cs>>>(dst, E);
    scan1_kernel<<<nb, SCAN_BLK, 0, cs>>>();
    scan3_kernel<<<(N_NODES + 255) / 256, 256, 0, cs>>>(nb);
    scatter_kernel<<<(E + 255) / 256, 256, 0, cs>>>(src, dst, E);
    gcnt_kernel<<<1, N_GRAPHS, 0, cs>>>(batch, N);
    if (forked) cudaEventRecord(ss.join, ss.s);

    // --- GEMM1 -> g_h1 (no ds dependency) ---
    gemm_kernel<IN_DIM, false><<<(N + 31) / 32, 128>>>(x, W1, nullptr, N);

    if (forked) cudaStreamWaitEvent(0, ss.join, 0);

    // --- layer-1 aggregation -> g_agg ---
    int agg_blocks = (int)(((long long)N * 32 + 255) / 256);
    agg_kernel<false><<<agg_blocks, 256>>>(batch, b2, N);

    // --- GEMM2 (relu(g_agg + b1) on load) -> g_h2 ---
    gemm_kernel<HID_DIM, true><<<(N + 31) / 32, 128>>>(nullptr, W2, b1, N);

    // --- layer-2 aggregation + bias + relu + mean-pool accumulate ---
    agg_kernel<true><<<agg_blocks, 256>>>(batch, b2, N);

    fc_kernel<<<N_GRAPHS, 64>>>(Wf1, bf1, Wf2, bf2, out);
}

// round 11
// speedup vs baseline: 1.3080x; 1.0741x over previous
#include <cuda_runtime.h>
#include <cuda_bf16.h>
#include <cstdint>
#include <cstring>

#define N_NODES   100000
#define N_EDGES_MAX 1600000
#define N_GRAPHS  256
#define IN_DIM    205
#define HID_DIM   128
#define FC_DIM    64
#define OUT_DIM   2
#define SCAN_BLK  1024

#define CH   48     // K-chunk per smem stage (3 MMA k-steps)
#define KPS  50     // smem row stride in bf16 (25 words, odd -> conflict-free)
#define KPW1 240    // padded K for W1 split (5 chunks)
#define KPW2 144    // padded K for W2 split (3 chunks)

// ---------------- scratch (static device globals; referenced ONLY from device code) ----------------
__device__ __align__(128) float g_h1[(size_t)N_NODES * HID_DIM];   // layer-1 GEMM output H1
__device__ __align__(128) float g_h2[(size_t)N_NODES * HID_DIM];   // layer-2 GEMM output H2
__device__ __align__(128) float g_agg[(size_t)N_NODES * HID_DIM];  // layer-1 aggregate (pre-bias)
__device__ int   g_degi[N_NODES];
__device__ int   g_rowstart[N_NODES];
__device__ int   g_cursor[N_NODES];
__device__ int   g_blocksum[128];
__device__ int   g_csrc[N_EDGES_MAX];
__device__ float g_ds[N_NODES];
__device__ float g_gsum[N_GRAPHS * HID_DIM];
__device__ float g_gcnt[N_GRAPHS];
// split-bf16 weights, [n][k_padded] layout (k contiguous per output feature)
__device__ __align__(128) __nv_bfloat16 g_w1hi[HID_DIM * KPW1];
__device__ __align__(128) __nv_bfloat16 g_w1lo[HID_DIM * KPW1];
__device__ __align__(128) __nv_bfloat16 g_w2hi[HID_DIM * KPW2];
__device__ __align__(128) __nv_bfloat16 g_w2lo[HID_DIM * KPW2];

// ---------------- helpers ----------------
__device__ __forceinline__ uint32_t ld32bf(const __nv_bfloat16* p) {
    return *reinterpret_cast<const uint32_t*>(p);
}
__device__ __forceinline__ void mma16816(float* d, const uint32_t* a, const uint32_t* b) {
    asm volatile("mma.sync.aligned.m16n8k16.row.col.f32.bf16.bf16.f32 "
                 "{%0,%1,%2,%3}, {%4,%5,%6,%7}, {%8,%9}, {%0,%1,%2,%3};"
                 : "+f"(d[0]), "+f"(d[1]), "+f"(d[2]), "+f"(d[3])
                 : "r"(a[0]), "r"(a[1]), "r"(a[2]), "r"(a[3]), "r"(b[0]), "r"(b[1]));
}

// ---------------- zero the small accumulators ----------------
__global__ void zero_kernel() {
    int i = blockIdx.x * blockDim.x + threadIdx.x;
    if (i < N_NODES) g_degi[i] = 0;
    if (i < N_GRAPHS * HID_DIM) g_gsum[i] = 0.0f;
}

// ---------------- weight split: W[K,128] -> hi/lo bf16 in [n][k_padded] ----------------
template <bool SECOND>
__global__ void wsplit_kernel(const float* __restrict__ W) {
    constexpr int K   = SECOND ? HID_DIM : IN_DIM;
    constexpr int KPW = SECOND ? KPW2 : KPW1;
    __nv_bfloat16* hi = SECOND ? g_w2hi : g_w1hi;
    __nv_bfloat16* lo = SECOND ? g_w2lo : g_w1lo;
    int idx = blockIdx.x * blockDim.x + threadIdx.x;
    if (idx >= KPW * HID_DIM) return;
    int kk = idx >> 7;            // /128
    int n  = idx & 127;
    float v = (kk < K) ? W[kk * HID_DIM + n] : 0.0f;
    __nv_bfloat16 h = __float2bfloat16(v);
    hi[n * KPW + kk] = h;
    lo[n * KPW + kk] = __float2bfloat16(v - __bfloat162float(h));
}

// ---------------- in-degree histogram ----------------
__global__ void hist_kernel(const int* __restrict__ dst, int E) {
    int e = blockIdx.x * blockDim.x + threadIdx.x;
    if (e < E) atomicAdd(&g_degi[dst[e]], 1);
}

// ---------------- scan level 1 ----------------
__global__ void scan1_kernel() {
    __shared__ int sh[SCAN_BLK];
    int i = blockIdx.x * SCAN_BLK + threadIdx.x;
    int v = (i < N_NODES) ? g_degi[i] : 0;
    sh[threadIdx.x] = v;
    __syncthreads();
    for (int off = 1; off < SCAN_BLK; off <<= 1) {
        int t = (threadIdx.x >= off) ? sh[threadIdx.x - off] : 0;
        __syncthreads();
        sh[threadIdx.x] += t;
        __syncthreads();
    }
    if (i < N_NODES) g_rowstart[i] = sh[threadIdx.x] - v;
    if (threadIdx.x == SCAN_BLK - 1) g_blocksum[blockIdx.x] = sh[threadIdx.x];
}

// -------- scan level 2 fused: parallel block-sum prefix; NO atomics --------
__global__ void scan3_kernel(int nb) {
    __shared__ int pref[256];
    int t = threadIdx.x;
    int v = (t < nb) ? g_blocksum[t] : 0;
    pref[t] = v;
    __syncthreads();
    for (int off = 1; off < 256; off <<= 1) {
        int u = (t >= off) ? pref[t - off] : 0;
        __syncthreads();
        pref[t] += u;
        __syncthreads();
    }
    int ex = pref[t] - v;
    __syncthreads();
    pref[t] = ex;
    __syncthreads();

    int i = blockIdx.x * blockDim.x + t;
    if (i >= N_NODES) return;
    int rs = g_rowstart[i] + pref[i / SCAN_BLK];
    g_rowstart[i] = rs;
    g_cursor[i] = rs;
    g_ds[i] = rsqrtf((float)g_degi[i] + 1.0f);
}

// ---------------- graph node counts via binary search on SORTED batch ----------------
__global__ void gcnt_kernel(const int* __restrict__ batch, int n) {
    __shared__ int lb[N_GRAPHS + 1];
    int g = threadIdx.x;
    int lo = 0, hi = n;
    while (lo < hi) {
        int mid = (lo + hi) >> 1;
        if (batch[mid] < g) lo = mid + 1; else hi = mid;
    }
    lb[g] = lo;
    if (g == 0) lb[N_GRAPHS] = n;
    __syncthreads();
    g_gcnt[g] = (float)(lb[g + 1] - lb[g]);
}

// ---------------- CSR scatter ----------------
__global__ void scatter_kernel(const int* __restrict__ src, const int* __restrict__ dst, int E) {
    int e = blockIdx.x * blockDim.x + threadIdx.x;
    if (e < E) {
        int pos = atomicAdd(&g_cursor[dst[e]], 1);
        g_csrc[pos] = src[e];
    }
}

// ---------------- split-bf16 MMA GEMM: OUT = in @ W ----------------
// PRE=false: in = X (global), W = g_w1*, OUT = g_h1.
// PRE=true : in = relu(g_agg + bias), W = g_w2*, OUT = g_h2.
// CTA: 64 rows x 128 cols, 256 threads = 8 warps (2 M x 4 N), warp tile 32x32.
// 3 products per k-step: hi*hi + hi*lo + lo*hi (fp32 accum) ~= fp32 precision.
template <int KTOT, int NCHUNK, bool PRE>
__global__ void __launch_bounds__(256) gemm_mma_kernel(const float* __restrict__ X,
                                                       const float* __restrict__ bias,
                                                       int N) {
    __shared__ __nv_bfloat16 xs_hi[64 * KPS], xs_lo[64 * KPS];
    __shared__ __nv_bfloat16 ws_hi[128 * KPS], ws_lo[128 * KPS];

    const float* in = PRE ? g_agg : X;
    float* OUT = PRE ? g_h2 : g_h1;
    const __nv_bfloat16* whi = PRE ? g_w2hi : g_w1hi;
    const __nv_bfloat16* wlo = PRE ? g_w2lo : g_w1lo;
    constexpr int KPW = NCHUNK * CH;

    int row0 = blockIdx.x * 64;
    int tid  = threadIdx.x;
    int lane = tid & 31;
    int warp = tid >> 5;
    int warp_m = warp & 1;      // 0..1 -> rows +0/+32
    int warp_n = warp >> 1;     // 0..3 -> cols +32*wn
    int g = lane >> 2;          // 0..7
    int q = lane & 3;           // 0..3

    float acc[2][4][4];
#pragma unroll
    for (int f = 0; f < 2; f++)
#pragma unroll
        for (int j = 0; j < 4; j++)
#pragma unroll
            for (int e = 0; e < 4; e++) acc[f][j][e] = 0.0f;

    for (int c = 0; c < NCHUNK; c++) {
        __syncthreads();
        // stage + split X rows for this K-chunk
        for (int idx = tid; idx < 64 * CH; idx += 256) {
            int m = idx / CH;
            int kk = idx - m * CH;
            int gk = c * CH + kk;
            int row = row0 + m;
            float v = 0.0f;
            if (row < N && gk < KTOT) {
                v = in[(size_t)row * KTOT + gk];
                if (PRE) v = fmaxf(v + bias[gk], 0.0f);
            }
            __nv_bfloat16 h = __float2bfloat16(v);
            xs_hi[m * KPS + kk] = h;
            xs_lo[m * KPS + kk] = __float2bfloat16(v - __bfloat162float(h));
        }
        // stage pre-split W chunk (u32 copies)
        for (int idx = tid; idx < 128 * (CH / 2); idx += 256) {
            int n = idx / (CH / 2);
            int kw = idx - n * (CH / 2);
            *reinterpret_cast<uint32_t*>(&ws_hi[n * KPS + kw * 2]) =
                *reinterpret_cast<const uint32_t*>(&whi[n * KPW + c * CH + kw * 2]);
            *reinterpret_cast<uint32_t*>(&ws_lo[n * KPS + kw * 2]) =
                *reinterpret_cast<const uint32_t*>(&wlo[n * KPW + c * CH + kw * 2]);
        }
        __syncthreads();

#pragma unroll
        for (int ks = 0; ks < CH / 16; ks++) {
            int k0 = ks * 16;
            uint32_t Ahi[2][4], Alo[2][4], Bhi[4][2], Blo[4][2];
#pragma unroll
            for (int f = 0; f < 2; f++) {
                int r = (warp_m * 32 + f * 16 + g) * KPS + k0 + q * 2;
                Ahi[f][0] = ld32bf(&xs_hi[r]);
                Ahi[f][1] = ld32bf(&xs_hi[r + 8 * KPS]);
                Ahi[f][2] = ld32bf(&xs_hi[r + 8]);
                Ahi[f][3] = ld32bf(&xs_hi[r + 8 * KPS + 8]);
                Alo[f][0] = ld32bf(&xs_lo[r]);
                Alo[f][1] = ld32bf(&xs_lo[r + 8 * KPS]);
                Alo[f][2] = ld32bf(&xs_lo[r + 8]);
                Alo[f][3] = ld32bf(&xs_lo[r + 8 * KPS + 8]);
            }
#pragma unroll
            for (int j = 0; j < 4; j++) {
                int nidx = (warp_n * 32 + j * 8 + g) * KPS + k0 + q * 2;
                Bhi[j][0] = ld32bf(&ws_hi[nidx]);
                Bhi[j][1] = ld32bf(&ws_hi[nidx + 8]);
                Blo[j][0] = ld32bf(&ws_lo[nidx]);
                Blo[j][1] = ld32bf(&ws_lo[nidx + 8]);
            }
#pragma unroll
            for (int f = 0; f < 2; f++)
#pragma unroll
                for (int j = 0; j < 4; j++) {
                    mma16816(acc[f][j], Ahi[f], Bhi[j]);
                    mma16816(acc[f][j], Ahi[f], Blo[j]);
                    mma16816(acc[f][j], Alo[f], Bhi[j]);
                }
        }
    }

    // epilogue: fragment -> global (float2 per pair)
#pragma unroll
    for (int f = 0; f < 2; f++) {
        int rb = row0 + warp_m * 32 + f * 16 + g;
#pragma unroll
        for (int j = 0; j < 4; j++) {
            int col = warp_n * 32 + j * 8 + q * 2;
            if (rb < N)
                *reinterpret_cast<float2*>(&OUT[(size_t)rb * HID_DIM + col]) =
                    make_float2(acc[f][j][0], acc[f][j][1]);
            if (rb + 8 < N)
                *reinterpret_cast<float2*>(&OUT[(size_t)(rb + 8) * HID_DIM + col]) =
                    make_float2(acc[f][j][2], acc[f][j][3]);
        }
    }
}

// ------- CSR aggregation: one warp per dst node; lane owns a float4 -------
template <bool FINAL>
__global__ void __launch_bounds__(256) agg_kernel(const int* __restrict__ batch,
                                                  const float* __restrict__ b2,
                                                  int n) {
    int node = (blockIdx.x * blockDim.x + threadIdx.x) >> 5;
    int lane = threadIdx.x & 31;
    if (node >= n) return;

    const float4* __restrict__ hs = reinterpret_cast<const float4*>(FINAL ? g_h2 : g_h1);
    float dsd = g_ds[node];
    float4 self = hs[(size_t)node * 32 + lane];
    float4 sum = make_float4(dsd * self.x, dsd * self.y, dsd * self.z, dsd * self.w);

    int start = g_rowstart[node];
    int deg = g_degi[node];

    for (int j0 = 0; j0 < deg; j0 += 32) {
        int idx = j0 + lane;
        int myid = (idx < deg) ? g_csrc[start + idx] : 0;
        float myds = g_ds[myid];
        int cnt = min(32, deg - j0);
#pragma unroll 4
        for (int k = 0; k < cnt; k++) {
            int s = __shfl_sync(0xffffffffu, myid, k);
            float dss = __shfl_sync(0xffffffffu, myds, k);
            float4 v = hs[(size_t)s * 32 + lane];
            sum.x = fmaf(dss, v.x, sum.x);
            sum.y = fmaf(dss, v.y, sum.y);
            sum.z = fmaf(dss, v.z, sum.z);
            sum.w = fmaf(dss, v.w, sum.w);
        }
    }

    if (!FINAL) {
        reinterpret_cast<float4*>(g_agg)[(size_t)node * 32 + lane] =
            make_float4(sum.x * dsd, sum.y * dsd, sum.z * dsd, sum.w * dsd);
    } else {
        float4 bv = reinterpret_cast<const float4*>(b2)[lane];
        float vx = fmaxf(fmaf(sum.x, dsd, bv.x), 0.0f);
        float vy = fmaxf(fmaf(sum.y, dsd, bv.y), 0.0f);
        float vz = fmaxf(fmaf(sum.z, dsd, bv.z), 0.0f);
        float vw = fmaxf(fmaf(sum.w, dsd, bv.w), 0.0f);
        float4* out = reinterpret_cast<float4*>(g_gsum) + batch[node] * 32 + lane;
        asm volatile("red.global.add.v4.f32 [%0], {%1, %2, %3, %4};"
                     :: "l"(out), "f"(vx), "f"(vy), "f"(vz), "f"(vw)
                     : "memory");
    }
}

// ---------------- FC head ----------------
__global__ void __launch_bounds__(64) fc_kernel(const float* __restrict__ Wf1,
                                                const float* __restrict__ bf1,
                                                const float* __restrict__ Wf2,
                                                const float* __restrict__ bf2,
                                                float* __restrict__ out) {
    __shared__ float grow[HID_DIM];
    __shared__ float a[FC_DIM];
    int g = blockIdx.x;
    int t = threadIdx.x;
    float inv = 1.0f / fmaxf(g_gcnt[g], 1.0f);
    grow[t] = g_gsum[g * HID_DIM + t] * inv;
    grow[t + 64] = g_gsum[g * HID_DIM + 64 + t] * inv;
    __syncthreads();
    float acc = bf1[t];
#pragma unroll 8
    for (int k = 0; k < HID_DIM; k++) acc += grow[k] * Wf1[k * FC_DIM + t];
    a[t] = fmaxf(acc, 0.0f);
    __syncthreads();
    if (t < OUT_DIM) {
        float o = bf2[t];
#pragma unroll 8
        for (int j = 0; j < FC_DIM; j++) o += a[j] * Wf2[j * OUT_DIM + t];
        out[g * OUT_DIM + t] = o;
    }
}

// ---------------- fork/join resources ----------------
struct SideStream {
    cudaStream_t s = nullptr;
    cudaEvent_t fork = nullptr, join = nullptr;
    SideStream() {
        if (cudaStreamCreateWithFlags(&s, cudaStreamNonBlocking) != cudaSuccess) { s = nullptr; return; }
        if (cudaEventCreateWithFlags(&fork, cudaEventDisableTiming) != cudaSuccess) { s = nullptr; return; }
        if (cudaEventCreateWithFlags(&join, cudaEventDisableTiming) != cudaSuccess) { s = nullptr; return; }
    }
};
static SideStream& side() { static SideStream ss; return ss; }

// ---------------- launcher ----------------
extern "C" void kernel_launch(void* const* d_in, const int* in_sizes, int n_in,
                              void* d_out, int out_size) {
    const float* x   = (const float*)d_in[0];
    const int* ei    = (const int*)d_in[1];   // [2, E] int32
    const int* batch = (const int*)d_in[2];
    const float* W1  = (const float*)d_in[3];
    const float* b1  = (const float*)d_in[4];
    const float* W2  = (const float*)d_in[5];
    const float* b2  = (const float*)d_in[6];
    const float* Wf1 = (const float*)d_in[7];
    const float* bf1 = (const float*)d_in[8];
    const float* Wf2 = (const float*)d_in[9];
    const float* bf2 = (const float*)d_in[10];
    float* out = (float*)d_out;

    int E = in_sizes[1] / 2;
    int N = in_sizes[2];
    const int* src = ei;
    const int* dst = ei + E;
    int nb = (N_NODES + SCAN_BLK - 1) / SCAN_BLK;

    SideStream& ss = side();
    bool forked = (ss.s != nullptr);
    cudaStream_t cs = forked ? ss.s : (cudaStream_t)0;

    if (forked) {
        cudaEventRecord(ss.fork, 0);
        cudaStreamWaitEvent(ss.s, ss.fork, 0);
    }

    // --- CSR build chain (side stream): independent of GEMM1 ---
    zero_kernel<<<(N_NODES + 255) / 256, 256, 0, cs>>>();
    hist_kernel<<<(E + 255) / 256, 256, 0, cs>>>(dst, E);
    scan1_kernel<<<nb, SCAN_BLK, 0, cs>>>();
    scan3_kernel<<<(N_NODES + 255) / 256, 256, 0, cs>>>(nb);
    scatter_kernel<<<(E + 255) / 256, 256, 0, cs>>>(src, dst, E);
    gcnt_kernel<<<1, N_GRAPHS, 0, cs>>>(batch, N);
    if (forked) cudaEventRecord(ss.join, ss.s);

    // --- weight splits (tiny) then GEMM1 -> g_h1 ---
    wsplit_kernel<false><<<(KPW1 * HID_DIM + 255) / 256, 256>>>(W1);
    wsplit_kernel<true><<<(KPW2 * HID_DIM + 255) / 256, 256>>>(W2);
    gemm_mma_kernel<IN_DIM, 5, false><<<(N + 63) / 64, 256>>>(x, nullptr, N);

    if (forked) cudaStreamWaitEvent(0, ss.join, 0);

    // --- layer-1 aggregation -> g_agg ---
    int agg_blocks = (int)(((long long)N * 32 + 255) / 256);
    agg_kernel<false><<<agg_blocks, 256>>>(batch, b2, N);

    // --- GEMM2 (relu(g_agg + b1) on load) -> g_h2 ---
    gemm_mma_kernel<HID_DIM, 3, true><<<(N + 63) / 64, 256>>>(nullptr, b1, N);

    // --- layer-2 aggregation + bias + relu + mean-pool accumulate ---
    agg_kernel<true><<<agg_blocks, 256>>>(batch, b2, N);

    fc_kernel<<<N_GRAPHS, 64>>>(Wf1, bf1, Wf2, bf2, out);
}

// round 12
// speedup vs baseline: 1.4017x; 1.0716x over previous
#include <cuda_runtime.h>
#include <cuda_bf16.h>
#include <cstdint>
#include <cstring>

#define N_NODES   100000
#define N_EDGES_MAX 1600000
#define N_GRAPHS  256
#define IN_DIM    205
#define HID_DIM   128
#define FC_DIM    64
#define OUT_DIM   2
#define SCAN_BLK  1024

#define CH   48     // K-chunk per smem stage (3 MMA k-steps)
#define KPS  56     // smem row stride in bf16 (112B = 7*16B: ldmatrix-aligned, conflict-free)
#define KPW1 240    // padded K for W1 split (5 chunks)
#define KPW2 144    // padded K for W2 split (3 chunks)

// ---------------- scratch (static device globals; referenced ONLY from device code) ----------------
__device__ __align__(128) float g_h1[(size_t)N_NODES * HID_DIM];   // layer-1 GEMM output H1
__device__ __align__(128) float g_h2[(size_t)N_NODES * HID_DIM];   // layer-2 GEMM output H2
__device__ __align__(128) float g_agg[(size_t)N_NODES * HID_DIM];  // layer-1 aggregate (pre-bias)
__device__ int   g_degi[N_NODES];
__device__ int   g_rowstart[N_NODES];
__device__ int   g_cursor[N_NODES];
__device__ int   g_blocksum[128];
__device__ int   g_csrc[N_EDGES_MAX];
__device__ float g_ds[N_NODES];
__device__ float g_gsum[N_GRAPHS * HID_DIM];
__device__ float g_gcnt[N_GRAPHS];
// split-bf16 weights, [n][k_padded] layout (k contiguous per output feature)
__device__ __align__(128) __nv_bfloat16 g_w1hi[HID_DIM * KPW1];
__device__ __align__(128) __nv_bfloat16 g_w1lo[HID_DIM * KPW1];
__device__ __align__(128) __nv_bfloat16 g_w2hi[HID_DIM * KPW2];
__device__ __align__(128) __nv_bfloat16 g_w2lo[HID_DIM * KPW2];

// ---------------- helpers ----------------
__device__ __forceinline__ uint32_t sptr(const void* p) {
    return (uint32_t)__cvta_generic_to_shared(p);
}
__device__ __forceinline__ void ldsm4(uint32_t* r, uint32_t addr) {
    asm volatile("ldmatrix.sync.aligned.m8n8.x4.shared.b16 {%0,%1,%2,%3}, [%4];"
                 : "=r"(r[0]), "=r"(r[1]), "=r"(r[2]), "=r"(r[3]) : "r"(addr));
}
__device__ __forceinline__ void mma16816(float* d, const uint32_t* a, const uint32_t* b) {
    asm volatile("mma.sync.aligned.m16n8k16.row.col.f32.bf16.bf16.f32 "
                 "{%0,%1,%2,%3}, {%4,%5,%6,%7}, {%8,%9}, {%0,%1,%2,%3};"
                 : "+f"(d[0]), "+f"(d[1]), "+f"(d[2]), "+f"(d[3])
                 : "r"(a[0]), "r"(a[1]), "r"(a[2]), "r"(a[3]), "r"(b[0]), "r"(b[1]));
}

// ---------------- zero the small accumulators ----------------
__global__ void zero_kernel() {
    int i = blockIdx.x * blockDim.x + threadIdx.x;
    if (i < N_NODES) g_degi[i] = 0;
    if (i < N_GRAPHS * HID_DIM) g_gsum[i] = 0.0f;
}

// ---------------- weight split: W[K,128] -> hi/lo bf16 in [n][k_padded] ----------------
template <bool SECOND>
__global__ void wsplit_kernel(const float* __restrict__ W) {
    constexpr int K   = SECOND ? HID_DIM : IN_DIM;
    constexpr int KPW = SECOND ? KPW2 : KPW1;
    __nv_bfloat16* hi = SECOND ? g_w2hi : g_w1hi;
    __nv_bfloat16* lo = SECOND ? g_w2lo : g_w1lo;
    int idx = blockIdx.x * blockDim.x + threadIdx.x;
    if (idx >= KPW * HID_DIM) return;
    int kk = idx >> 7;            // /128
    int n  = idx & 127;
    float v = (kk < K) ? W[kk * HID_DIM + n] : 0.0f;
    __nv_bfloat16 h = __float2bfloat16(v);
    hi[n * KPW + kk] = h;
    lo[n * KPW + kk] = __float2bfloat16(v - __bfloat162float(h));
}

// ---------------- in-degree histogram ----------------
__global__ void hist_kernel(const int* __restrict__ dst, int E) {
    int e = blockIdx.x * blockDim.x + threadIdx.x;
    if (e < E) atomicAdd(&g_degi[dst[e]], 1);
}

// ---------------- scan level 1 ----------------
__global__ void scan1_kernel() {
    __shared__ int sh[SCAN_BLK];
    int i = blockIdx.x * SCAN_BLK + threadIdx.x;
    int v = (i < N_NODES) ? g_degi[i] : 0;
    sh[threadIdx.x] = v;
    __syncthreads();
    for (int off = 1; off < SCAN_BLK; off <<= 1) {
        int t = (threadIdx.x >= off) ? sh[threadIdx.x - off] : 0;
        __syncthreads();
        sh[threadIdx.x] += t;
        __syncthreads();
    }
    if (i < N_NODES) g_rowstart[i] = sh[threadIdx.x] - v;
    if (threadIdx.x == SCAN_BLK - 1) g_blocksum[blockIdx.x] = sh[threadIdx.x];
}

// -------- scan level 2 fused: parallel block-sum prefix; NO atomics --------
__global__ void scan3_kernel(int nb) {
    __shared__ int pref[256];
    int t = threadIdx.x;
    int v = (t < nb) ? g_blocksum[t] : 0;
    pref[t] = v;
    __syncthreads();
    for (int off = 1; off < 256; off <<= 1) {
        int u = (t >= off) ? pref[t - off] : 0;
        __syncthreads();
        pref[t] += u;
        __syncthreads();
    }
    int ex = pref[t] - v;
    __syncthreads();
    pref[t] = ex;
    __syncthreads();

    int i = blockIdx.x * blockDim.x + t;
    if (i >= N_NODES) return;
    int rs = g_rowstart[i] + pref[i / SCAN_BLK];
    g_rowstart[i] = rs;
    g_cursor[i] = rs;
    g_ds[i] = rsqrtf((float)g_degi[i] + 1.0f);
}

// ---------------- graph node counts via binary search on SORTED batch ----------------
__global__ void gcnt_kernel(const int* __restrict__ batch, int n) {
    __shared__ int lb[N_GRAPHS + 1];
    int g = threadIdx.x;
    int lo = 0, hi = n;
    while (lo < hi) {
        int mid = (lo + hi) >> 1;
        if (batch[mid] < g) lo = mid + 1; else hi = mid;
    }
    lb[g] = lo;
    if (g == 0) lb[N_GRAPHS] = n;
    __syncthreads();
    g_gcnt[g] = (float)(lb[g + 1] - lb[g]);
}

// ---------------- CSR scatter ----------------
__global__ void scatter_kernel(const int* __restrict__ src, const int* __restrict__ dst, int E) {
    int e = blockIdx.x * blockDim.x + threadIdx.x;
    if (e < E) {
        int pos = atomicAdd(&g_cursor[dst[e]], 1);
        g_csrc[pos] = src[e];
    }
}

// ---------------- split-bf16 MMA GEMM with ldmatrix: OUT = in @ W ----------------
// PRE=false: in = X (global), W = g_w1*, OUT = g_h1.
// PRE=true : in = relu(g_agg + bias), W = g_w2*, OUT = g_h2.
// CTA: 64 rows x 128 cols, 256 threads = 8 warps (2 M x 4 N), warp tile 32x32.
// 3 products per k-step: hi*hi + hi*lo + lo*hi (fp32 accum) ~= fp32 precision.
template <int KTOT, int NCHUNK, bool PRE>
__global__ void __launch_bounds__(256) gemm_mma_kernel(const float* __restrict__ X,
                                                       const float* __restrict__ bias,
                                                       int N) {
    __shared__ __align__(128) __nv_bfloat16 xs_hi[64 * KPS], xs_lo[64 * KPS];
    __shared__ __align__(128) __nv_bfloat16 ws_hi[128 * KPS], ws_lo[128 * KPS];

    const float* in = PRE ? g_agg : X;
    float* OUT = PRE ? g_h2 : g_h1;
    const __nv_bfloat16* whi = PRE ? g_w2hi : g_w1hi;
    const __nv_bfloat16* wlo = PRE ? g_w2lo : g_w1lo;
    constexpr int KPW = NCHUNK * CH;

    int row0 = blockIdx.x * 64;
    int tid  = threadIdx.x;
    int lane = tid & 31;
    int warp = tid >> 5;
    int warp_m = warp & 1;      // 0..1 -> rows +0/+32
    int warp_n = warp >> 1;     // 0..3 -> cols +32*wn
    int g = lane >> 2;          // 0..7
    int q = lane & 3;           // 0..3

    // ldmatrix per-lane source rows/cols
    int a_row = warp_m * 32 + (lane & 7) + ((lane >> 3) & 1) * 8;   // + f*16
    int a_kof = ((lane >> 4) & 1) * 8;                               // + k0
    int b_row = warp_n * 32 + (lane & 7) + ((lane >> 4) & 1) * 8;   // + jp*16
    int b_kof = ((lane >> 3) & 1) * 8;                               // + k0

    float acc[2][4][4];
#pragma unroll
    for (int f = 0; f < 2; f++)
#pragma unroll
        for (int j = 0; j < 4; j++)
#pragma unroll
            for (int e = 0; e < 4; e++) acc[f][j][e] = 0.0f;

    for (int c = 0; c < NCHUNK; c++) {
        __syncthreads();
        // stage + split X rows for this K-chunk
        for (int idx = tid; idx < 64 * CH; idx += 256) {
            int m = idx / CH;
            int kk = idx - m * CH;
            int gk = c * CH + kk;
            int row = row0 + m;
            float v = 0.0f;
            if (row < N && gk < KTOT) {
                v = in[(size_t)row * KTOT + gk];
                if (PRE) v = fmaxf(v + bias[gk], 0.0f);
            }
            __nv_bfloat16 h = __float2bfloat16(v);
            xs_hi[m * KPS + kk] = h;
            xs_lo[m * KPS + kk] = __float2bfloat16(v - __bfloat162float(h));
        }
        // stage pre-split W chunk (u32 copies)
        for (int idx = tid; idx < 128 * (CH / 2); idx += 256) {
            int n = idx / (CH / 2);
            int kw = idx - n * (CH / 2);
            *reinterpret_cast<uint32_t*>(&ws_hi[n * KPS + kw * 2]) =
                *reinterpret_cast<const uint32_t*>(&whi[n * KPW + c * CH + kw * 2]);
            *reinterpret_cast<uint32_t*>(&ws_lo[n * KPS + kw * 2]) =
                *reinterpret_cast<const uint32_t*>(&wlo[n * KPW + c * CH + kw * 2]);
        }
        __syncthreads();

#pragma unroll
        for (int ks = 0; ks < CH / 16; ks++) {
            int k0 = ks * 16;
            uint32_t Ahi[2][4], Alo[2][4], Bhi[4][2], Blo[4][2];
#pragma unroll
            for (int f = 0; f < 2; f++) {
                int r = (a_row + f * 16) * KPS + k0 + a_kof;
                ldsm4(Ahi[f], sptr(&xs_hi[r]));
                ldsm4(Alo[f], sptr(&xs_lo[r]));
            }
#pragma unroll
            for (int jp = 0; jp < 2; jp++) {
                int r = (b_row + jp * 16) * KPS + k0 + b_kof;
                uint32_t t[4];
                ldsm4(t, sptr(&ws_hi[r]));
                Bhi[jp * 2][0] = t[0]; Bhi[jp * 2][1] = t[1];
                Bhi[jp * 2 + 1][0] = t[2]; Bhi[jp * 2 + 1][1] = t[3];
                ldsm4(t, sptr(&ws_lo[r]));
                Blo[jp * 2][0] = t[0]; Blo[jp * 2][1] = t[1];
                Blo[jp * 2 + 1][0] = t[2]; Blo[jp * 2 + 1][1] = t[3];
            }
#pragma unroll
            for (int f = 0; f < 2; f++)
#pragma unroll
                for (int j = 0; j < 4; j++) {
                    mma16816(acc[f][j], Ahi[f], Bhi[j]);
                    mma16816(acc[f][j], Ahi[f], Blo[j]);
                    mma16816(acc[f][j], Alo[f], Bhi[j]);
                }
        }
    }

    // epilogue: fragment -> global (float2 per pair)
#pragma unroll
    for (int f = 0; f < 2; f++) {
        int rb = row0 + warp_m * 32 + f * 16 + g;
#pragma unroll
        for (int j = 0; j < 4; j++) {
            int col = warp_n * 32 + j * 8 + q * 2;
            if (rb < N)
                *reinterpret_cast<float2*>(&OUT[(size_t)rb * HID_DIM + col]) =
                    make_float2(acc[f][j][0], acc[f][j][1]);
            if (rb + 8 < N)
                *reinterpret_cast<float2*>(&OUT[(size_t)(rb + 8) * HID_DIM + col]) =
                    make_float2(acc[f][j][2], acc[f][j][3]);
        }
    }
}

// ------- CSR aggregation: one warp per dst node; lane owns a float4 -------
template <bool FINAL>
__global__ void __launch_bounds__(256) agg_kernel(const int* __restrict__ batch,
                                                  const float* __restrict__ b2,
                                                  int n) {
    int node = (blockIdx.x * blockDim.x + threadIdx.x) >> 5;
    int lane = threadIdx.x & 31;
    if (node >= n) return;

    const float4* __restrict__ hs = reinterpret_cast<const float4*>(FINAL ? g_h2 : g_h1);
    float dsd = g_ds[node];
    float4 self = hs[(size_t)node * 32 + lane];
    float4 sum = make_float4(dsd * self.x, dsd * self.y, dsd * self.z, dsd * self.w);

    int start = g_rowstart[node];
    int deg = g_degi[node];

    for (int j0 = 0; j0 < deg; j0 += 32) {
        int idx = j0 + lane;
        int myid = (idx < deg) ? g_csrc[start + idx] : 0;
        float myds = g_ds[myid];
        int cnt = min(32, deg - j0);
#pragma unroll 4
        for (int k = 0; k < cnt; k++) {
            int s = __shfl_sync(0xffffffffu, myid, k);
            float dss = __shfl_sync(0xffffffffu, myds, k);
            float4 v = hs[(size_t)s * 32 + lane];
            sum.x = fmaf(dss, v.x, sum.x);
            sum.y = fmaf(dss, v.y, sum.y);
            sum.z = fmaf(dss, v.z, sum.z);
            sum.w = fmaf(dss, v.w, sum.w);
        }
    }

    if (!FINAL) {
        reinterpret_cast<float4*>(g_agg)[(size_t)node * 32 + lane] =
            make_float4(sum.x * dsd, sum.y * dsd, sum.z * dsd, sum.w * dsd);
    } else {
        float4 bv = reinterpret_cast<const float4*>(b2)[lane];
        float vx = fmaxf(fmaf(sum.x, dsd, bv.x), 0.0f);
        float vy = fmaxf(fmaf(sum.y, dsd, bv.y), 0.0f);
        float vz = fmaxf(fmaf(sum.z, dsd, bv.z), 0.0f);
        float vw = fmaxf(fmaf(sum.w, dsd, bv.w), 0.0f);
        float4* out = reinterpret_cast<float4*>(g_gsum) + batch[node] * 32 + lane;
        asm volatile("red.global.add.v4.f32 [%0], {%1, %2, %3, %4};"
                     :: "l"(out), "f"(vx), "f"(vy), "f"(vz), "f"(vw)
                     : "memory");
    }
}

// ---------------- FC head ----------------
__global__ void __launch_bounds__(64) fc_kernel(const float* __restrict__ Wf1,
                                                const float* __restrict__ bf1,
                                                const float* __restrict__ Wf2,
                                                const float* __restrict__ bf2,
                                                float* __restrict__ out) {
    __shared__ float grow[HID_DIM];
    __shared__ float a[FC_DIM];
    int g = blockIdx.x;
    int t = threadIdx.x;
    float inv = 1.0f / fmaxf(g_gcnt[g], 1.0f);
    grow[t] = g_gsum[g * HID_DIM + t] * inv;
    grow[t + 64] = g_gsum[g * HID_DIM + 64 + t] * inv;
    __syncthreads();
    float acc = bf1[t];
#pragma unroll 8
    for (int k = 0; k < HID_DIM; k++) acc += grow[k] * Wf1[k * FC_DIM + t];
    a[t] = fmaxf(acc, 0.0f);
    __syncthreads();
    if (t < OUT_DIM) {
        float o = bf2[t];
#pragma unroll 8
        for (int j = 0; j < FC_DIM; j++) o += a[j] * Wf2[j * OUT_DIM + t];
        out[g * OUT_DIM + t] = o;
    }
}

// ---------------- fork/join resources ----------------
struct SideStream {
    cudaStream_t s = nullptr;
    cudaEvent_t fork = nullptr, join = nullptr;
    SideStream() {
        if (cudaStreamCreateWithFlags(&s, cudaStreamNonBlocking) != cudaSuccess) { s = nullptr; return; }
        if (cudaEventCreateWithFlags(&fork, cudaEventDisableTiming) != cudaSuccess) { s = nullptr; return; }
        if (cudaEventCreateWithFlags(&join, cudaEventDisableTiming) != cudaSuccess) { s = nullptr; return; }
    }
};
static SideStream& side() { static SideStream ss; return ss; }

// ---------------- launcher ----------------
extern "C" void kernel_launch(void* const* d_in, const int* in_sizes, int n_in,
                              void* d_out, int out_size) {
    const float* x   = (const float*)d_in[0];
    const int* ei    = (const int*)d_in[1];   // [2, E] int32
    const int* batch = (const int*)d_in[2];
    const float* W1  = (const float*)d_in[3];
    const float* b1  = (const float*)d_in[4];
    const float* W2  = (const float*)d_in[5];
    const float* b2  = (const float*)d_in[6];
    const float* Wf1 = (const float*)d_in[7];
    const float* bf1 = (const float*)d_in[8];
    const float* Wf2 = (const float*)d_in[9];
    const float* bf2 = (const float*)d_in[10];
    float* out = (float*)d_out;

    int E = in_sizes[1] / 2;
    int N = in_sizes[2];
    const int* src = ei;
    const int* dst = ei + E;
    int nb = (N_NODES + SCAN_BLK - 1) / SCAN_BLK;

    SideStream& ss = side();
    bool forked = (ss.s != nullptr);
    cudaStream_t cs = forked ? ss.s : (cudaStream_t)0;

    if (forked) {
        cudaEventRecord(ss.fork, 0);
        cudaStreamWaitEvent(ss.s, ss.fork, 0);
    }

    // --- CSR build chain (side stream): independent of GEMM1 ---
    zero_kernel<<<(N_NODES + 255) / 256, 256, 0, cs>>>();
    hist_kernel<<<(E + 255) / 256, 256, 0, cs>>>(dst, E);
    scan1_kernel<<<nb, SCAN_BLK, 0, cs>>>();
    scan3_kernel<<<(N_NODES + 255) / 256, 256, 0, cs>>>(nb);
    scatter_kernel<<<(E + 255) / 256, 256, 0, cs>>>(src, dst, E);
    gcnt_kernel<<<1, N_GRAPHS, 0, cs>>>(batch, N);
    if (forked) cudaEventRecord(ss.join, ss.s);

    // --- weight splits (tiny) then GEMM1 -> g_h1 ---
    wsplit_kernel<false><<<(KPW1 * HID_DIM + 255) / 256, 256>>>(W1);
    wsplit_kernel<true><<<(KPW2 * HID_DIM + 255) / 256, 256>>>(W2);
    gemm_mma_kernel<IN_DIM, 5, false><<<(N + 63) / 64, 256>>>(x, nullptr, N);

    if (forked) cudaStreamWaitEvent(0, ss.join, 0);

    // --- layer-1 aggregation -> g_agg ---
    int agg_blocks = (int)(((long long)N * 32 + 255) / 256);
    agg_kernel<false><<<agg_blocks, 256>>>(batch, b2, N);

    // --- GEMM2 (relu(g_agg + b1) on load) -> g_h2 ---
    gemm_mma_kernel<HID_DIM, 3, true><<<(N + 63) / 64, 256>>>(nullptr, b1, N);

    // --- layer-2 aggregation + bias + relu + mean-pool accumulate ---
    agg_kernel<true><<<agg_blocks, 256>>>(batch, b2, N);

    fc_kernel<<<N_GRAPHS, 64>>>(Wf1, bf1, Wf2, bf2, out);
}

// round 13
// speedup vs baseline: 1.4059x; 1.0030x over previous
#include <cuda_runtime.h>
#include <cuda_bf16.h>
#include <cstdint>
#include <cstring>

#define N_NODES   100000
#define N_PAD     100032    // rounded up to 64
#define N_EDGES_MAX 1600000
#define N_GRAPHS  256
#define IN_DIM    205
#define HID_DIM   128
#define FC_DIM    64
#define OUT_DIM   2
#define SCAN_BLK  1024

#define CH    48    // K-chunk per smem stage (3 MMA k-steps)
#define KPS   56    // smem row stride in bf16 (112B = 7*16B)
#define KPW1  240   // padded K for layer-1 (5 chunks), 30 uint4/row
#define KPW2  144   // padded K for layer-2 (3 chunks), 18 uint4/row

// ---------------- scratch (static device globals; referenced ONLY from device code) ----------------
__device__ __align__(128) float g_h1[(size_t)N_PAD * HID_DIM];   // layer-1 GEMM output (fp32)
__device__ __align__(128) float g_h2[(size_t)N_PAD * HID_DIM];   // layer-2 GEMM output (fp32)
__device__ __align__(128) uint32_t g_x1hi[(size_t)N_PAD * (KPW1 / 2)];  // X split hi (bf16 pairs)
__device__ __align__(128) uint32_t g_x1lo[(size_t)N_PAD * (KPW1 / 2)];
__device__ __align__(128) uint32_t g_aghi[(size_t)N_PAD * (KPW2 / 2)];  // relu(agg1+b1) split hi
__device__ __align__(128) uint32_t g_aglo[(size_t)N_PAD * (KPW2 / 2)];
__device__ int   g_degi[N_NODES];
__device__ int   g_rowstart[N_NODES];
__device__ int   g_cursor[N_NODES];
__device__ int   g_blocksum[128];
__device__ int   g_csrc[N_EDGES_MAX];
__device__ float g_ds[N_NODES];
__device__ float g_gsum[N_GRAPHS * HID_DIM];
__device__ float g_gcnt[N_GRAPHS];
// split-bf16 weights, [n][k_padded] layout
__device__ __align__(128) __nv_bfloat16 g_w1hi[HID_DIM * KPW1];
__device__ __align__(128) __nv_bfloat16 g_w1lo[HID_DIM * KPW1];
__device__ __align__(128) __nv_bfloat16 g_w2hi[HID_DIM * KPW2];
__device__ __align__(128) __nv_bfloat16 g_w2lo[HID_DIM * KPW2];

// ---------------- helpers ----------------
__device__ __forceinline__ uint32_t sptr(const void* p) {
    return (uint32_t)__cvta_generic_to_shared(p);
}
__device__ __forceinline__ void ldsm4(uint32_t* r, uint32_t addr) {
    asm volatile("ldmatrix.sync.aligned.m8n8.x4.shared.b16 {%0,%1,%2,%3}, [%4];"
                 : "=r"(r[0]), "=r"(r[1]), "=r"(r[2]), "=r"(r[3]) : "r"(addr));
}
__device__ __forceinline__ void mma16816(float* d, const uint32_t* a, const uint32_t* b) {
    asm volatile("mma.sync.aligned.m16n8k16.row.col.f32.bf16.bf16.f32 "
                 "{%0,%1,%2,%3}, {%4,%5,%6,%7}, {%8,%9}, {%0,%1,%2,%3};"
                 : "+f"(d[0]), "+f"(d[1]), "+f"(d[2]), "+f"(d[3])
                 : "r"(a[0]), "r"(a[1]), "r"(a[2]), "r"(a[3]), "r"(b[0]), "r"(b[1]));
}
__device__ __forceinline__ void cpasync16(uint32_t dst, const void* src) {
    asm volatile("cp.async.cg.shared.global [%0], [%1], 16;" :: "r"(dst), "l"(src));
}
__device__ __forceinline__ uint32_t packbf(float a, float b) {
    return (uint32_t)__bfloat16_as_ushort(__float2bfloat16(a)) |
           ((uint32_t)__bfloat16_as_ushort(__float2bfloat16(b)) << 16);
}

// ---------------- zero the small accumulators ----------------
__global__ void zero_kernel() {
    int i = blockIdx.x * blockDim.x + threadIdx.x;
    if (i < N_NODES) g_degi[i] = 0;
    if (i < N_GRAPHS * HID_DIM) g_gsum[i] = 0.0f;
}

// ---------------- X split: fp32 [N][205] -> bf16 hi/lo pairs [N][120 u32] ----------------
__global__ void xsplit_kernel(const float* __restrict__ X, int n) {
    int idx = blockIdx.x * blockDim.x + threadIdx.x;
    int total = n * (KPW1 / 2);
    if (idx >= total) return;
    int row = idx / (KPW1 / 2);
    int kp  = idx - row * (KPW1 / 2);
    int k0 = kp * 2;
    float v0 = (k0 < IN_DIM) ? X[(size_t)row * IN_DIM + k0] : 0.0f;
    float v1 = (k0 + 1 < IN_DIM) ? X[(size_t)row * IN_DIM + k0 + 1] : 0.0f;
    __nv_bfloat16 h0 = __float2bfloat16(v0), h1 = __float2bfloat16(v1);
    g_x1hi[idx] = (uint32_t)__bfloat16_as_ushort(h0) | ((uint32_t)__bfloat16_as_ushort(h1) << 16);
    g_x1lo[idx] = packbf(v0 - __bfloat162float(h0), v1 - __bfloat162float(h1));
}

// ---------------- weight split: W[K,128] -> hi/lo bf16 in [n][k_padded] ----------------
template <bool SECOND>
__global__ void wsplit_kernel(const float* __restrict__ W) {
    constexpr int K   = SECOND ? HID_DIM : IN_DIM;
    constexpr int KPW = SECOND ? KPW2 : KPW1;
    __nv_bfloat16* hi = SECOND ? g_w2hi : g_w1hi;
    __nv_bfloat16* lo = SECOND ? g_w2lo : g_w1lo;
    int idx = blockIdx.x * blockDim.x + threadIdx.x;
    if (idx >= KPW * HID_DIM) return;
    int kk = idx >> 7;
    int n  = idx & 127;
    float v = (kk < K) ? W[kk * HID_DIM + n] : 0.0f;
    __nv_bfloat16 h = __float2bfloat16(v);
    hi[n * KPW + kk] = h;
    lo[n * KPW + kk] = __float2bfloat16(v - __bfloat162float(h));
}

// ---------------- in-degree histogram ----------------
__global__ void hist_kernel(const int* __restrict__ dst, int E) {
    int e = blockIdx.x * blockDim.x + threadIdx.x;
    if (e < E) atomicAdd(&g_degi[dst[e]], 1);
}

// ---------------- scan level 1 ----------------
__global__ void scan1_kernel() {
    __shared__ int sh[SCAN_BLK];
    int i = blockIdx.x * SCAN_BLK + threadIdx.x;
    int v = (i < N_NODES) ? g_degi[i] : 0;
    sh[threadIdx.x] = v;
    __syncthreads();
    for (int off = 1; off < SCAN_BLK; off <<= 1) {
        int t = (threadIdx.x >= off) ? sh[threadIdx.x - off] : 0;
        __syncthreads();
        sh[threadIdx.x] += t;
        __syncthreads();
    }
    if (i < N_NODES) g_rowstart[i] = sh[threadIdx.x] - v;
    if (threadIdx.x == SCAN_BLK - 1) g_blocksum[blockIdx.x] = sh[threadIdx.x];
}

// -------- scan level 2 fused: parallel block-sum prefix; NO atomics --------
__global__ void scan3_kernel(int nb) {
    __shared__ int pref[256];
    int t = threadIdx.x;
    int v = (t < nb) ? g_blocksum[t] : 0;
    pref[t] = v;
    __syncthreads();
    for (int off = 1; off < 256; off <<= 1) {
        int u = (t >= off) ? pref[t - off] : 0;
        __syncthreads();
        pref[t] += u;
        __syncthreads();
    }
    int ex = pref[t] - v;
    __syncthreads();
    pref[t] = ex;
    __syncthreads();

    int i = blockIdx.x * blockDim.x + t;
    if (i >= N_NODES) return;
    int rs = g_rowstart[i] + pref[i / SCAN_BLK];
    g_rowstart[i] = rs;
    g_cursor[i] = rs;
    g_ds[i] = rsqrtf((float)g_degi[i] + 1.0f);
}

// ---------------- graph node counts via binary search on SORTED batch ----------------
__global__ void gcnt_kernel(const int* __restrict__ batch, int n) {
    __shared__ int lb[N_GRAPHS + 1];
    int g = threadIdx.x;
    int lo = 0, hi = n;
    while (lo < hi) {
        int mid = (lo + hi) >> 1;
        if (batch[mid] < g) lo = mid + 1; else hi = mid;
    }
    lb[g] = lo;
    if (g == 0) lb[N_GRAPHS] = n;
    __syncthreads();
    g_gcnt[g] = (float)(lb[g + 1] - lb[g]);
}

// ---------------- CSR scatter ----------------
__global__ void scatter_kernel(const int* __restrict__ src, const int* __restrict__ dst, int E) {
    int e = blockIdx.x * blockDim.x + threadIdx.x;
    if (e < E) {
        int pos = atomicAdd(&g_cursor[dst[e]], 1);
        g_csrc[pos] = src[e];
    }
}

// ---------------- split-bf16 MMA GEMM, cp.async double-buffered ----------------
// PRE=false: in = g_x1hi/lo (stride 30 u4), W = g_w1*, OUT = g_h1.
// PRE=true : in = g_aghi/lo (stride 18 u4), W = g_w2*, OUT = g_h2.
// CTA: 64 rows x 128 cols, 256 threads = 8 warps (2 M x 4 N), warp tile 32x32.
template <int NCHUNK, int SRC_U4, bool PRE>
__global__ void __launch_bounds__(256) gemm_mma_kernel(int N) {
    extern __shared__ __align__(128) uint4 smem[];
    constexpr int XS_U4 = 64 * 7;    // per array per stage (uint4 units)
    constexpr int WS_U4 = 128 * 7;
    constexpr int STAGE_U4 = 2 * XS_U4 + 2 * WS_U4;   // 2688 u4 = 43008 B

    const uint4* xin_hi = reinterpret_cast<const uint4*>(PRE ? g_aghi : g_x1hi);
    const uint4* xin_lo = reinterpret_cast<const uint4*>(PRE ? g_aglo : g_x1lo);
    const uint4* win_hi = reinterpret_cast<const uint4*>(PRE ? g_w2hi : g_w1hi);
    const uint4* win_lo = reinterpret_cast<const uint4*>(PRE ? g_w2lo : g_w1lo);
    float* OUT = PRE ? g_h2 : g_h1;

    int row0 = blockIdx.x * 64;
    int tid  = threadIdx.x;
    int lane = tid & 31;
    int warp = tid >> 5;
    int warp_m = warp & 1;
    int warp_n = warp >> 1;
    int g = lane >> 2;
    int q = lane & 3;

    int a_row = warp_m * 32 + (lane & 7) + ((lane >> 3) & 1) * 8;
    int a_kof = ((lane >> 4) & 1) * 8;
    int b_row = warp_n * 32 + (lane & 7) + ((lane >> 4) & 1) * 8;
    int b_kof = ((lane >> 3) & 1) * 8;

    // prefetch chunk c into stage s (16B cp.async copies)
    auto prefetch = [&](int c, int s) {
        uint4* base = smem + s * STAGE_U4;
        // xs: 64 rows x 6 u4 x 2 arrays
        for (int idx = tid; idx < 768; idx += 256) {
            int row = idx / 12;
            int r2 = idx - row * 12;
            int arr = r2 / 6;
            int j = r2 - arr * 6;
            const uint4* src = (arr ? xin_lo : xin_hi) + (size_t)(row0 + row) * SRC_U4 + c * 6 + j;
            uint4* dst = base + arr * XS_U4 + row * 7 + j;
            cpasync16(sptr(dst), src);
        }
        // ws: 128 rows x 6 u4 x 2 arrays
        for (int idx = tid; idx < 1536; idx += 256) {
            int row = idx / 12;
            int r2 = idx - row * 12;
            int arr = r2 / 6;
            int j = r2 - arr * 6;
            const uint4* src = (arr ? win_lo : win_hi) + (size_t)row * SRC_U4 + c * 6 + j;
            uint4* dst = base + 2 * XS_U4 + arr * WS_U4 + row * 7 + j;
            cpasync16(sptr(dst), src);
        }
    };

    float acc[2][4][4];
#pragma unroll
    for (int f = 0; f < 2; f++)
#pragma unroll
        for (int j = 0; j < 4; j++)
#pragma unroll
            for (int e = 0; e < 4; e++) acc[f][j][e] = 0.0f;

    prefetch(0, 0);
    asm volatile("cp.async.commit_group;");

    for (int c = 0; c < NCHUNK; c++) {
        int s = c & 1;
        if (c + 1 < NCHUNK) prefetch(c + 1, (c + 1) & 1);
        asm volatile("cp.async.commit_group;");
        asm volatile("cp.async.wait_group 1;");
        __syncthreads();

        const __nv_bfloat16* xs_hi = reinterpret_cast<const __nv_bfloat16*>(smem + s * STAGE_U4);
        const __nv_bfloat16* xs_lo = xs_hi + XS_U4 * 8;
        const __nv_bfloat16* ws_hi = xs_hi + 2 * XS_U4 * 8;
        const __nv_bfloat16* ws_lo = xs_hi + (2 * XS_U4 + WS_U4) * 8;

#pragma unroll
        for (int ks = 0; ks < CH / 16; ks++) {
            int k0 = ks * 16;
            uint32_t Ahi[2][4], Alo[2][4], Bhi[4][2], Blo[4][2];
#pragma unroll
            for (int f = 0; f < 2; f++) {
                int r = (a_row + f * 16) * KPS + k0 + a_kof;
                ldsm4(Ahi[f], sptr(&xs_hi[r]));
                ldsm4(Alo[f], sptr(&xs_lo[r]));
            }
#pragma unroll
            for (int jp = 0; jp < 2; jp++) {
                int r = (b_row + jp * 16) * KPS + k0 + b_kof;
                uint32_t t[4];
                ldsm4(t, sptr(&ws_hi[r]));
                Bhi[jp * 2][0] = t[0]; Bhi[jp * 2][1] = t[1];
                Bhi[jp * 2 + 1][0] = t[2]; Bhi[jp * 2 + 1][1] = t[3];
                ldsm4(t, sptr(&ws_lo[r]));
                Blo[jp * 2][0] = t[0]; Blo[jp * 2][1] = t[1];
                Blo[jp * 2 + 1][0] = t[2]; Blo[jp * 2 + 1][1] = t[3];
            }
#pragma unroll
            for (int f = 0; f < 2; f++)
#pragma unroll
                for (int j = 0; j < 4; j++) {
                    mma16816(acc[f][j], Ahi[f], Bhi[j]);
                    mma16816(acc[f][j], Ahi[f], Blo[j]);
                    mma16816(acc[f][j], Alo[f], Bhi[j]);
                }
        }
        __syncthreads();
    }

    // epilogue: fragment -> global
#pragma unroll
    for (int f = 0; f < 2; f++) {
        int rb = row0 + warp_m * 32 + f * 16 + g;
#pragma unroll
        for (int j = 0; j < 4; j++) {
            int col = warp_n * 32 + j * 8 + q * 2;
            if (rb < N)
                *reinterpret_cast<float2*>(&OUT[(size_t)rb * HID_DIM + col]) =
                    make_float2(acc[f][j][0], acc[f][j][1]);
            if (rb + 8 < N)
                *reinterpret_cast<float2*>(&OUT[(size_t)(rb + 8) * HID_DIM + col]) =
                    make_float2(acc[f][j][2], acc[f][j][3]);
        }
    }
}

// ------- CSR aggregation: one warp per dst node; lane owns a float4 -------
// FINAL=false: relu(ds[d]*(sum ds[s]*H1[s] + ds[d]*H1[d]) + b1) -> split bf16 hi/lo [N][KPW2]
// FINAL=true : relu(same over H2 + b2) -> RED into g_gsum[batch[d]]
template <bool FINAL>
__global__ void __launch_bounds__(256) agg_kernel(const int* __restrict__ batch,
                                                  const float* __restrict__ bias,
                                                  int n) {
    int node = (blockIdx.x * blockDim.x + threadIdx.x) >> 5;
    int lane = threadIdx.x & 31;
    if (node >= n) return;

    const float4* __restrict__ hs = reinterpret_cast<const float4*>(FINAL ? g_h2 : g_h1);
    float dsd = g_ds[node];
    float4 self = hs[(size_t)node * 32 + lane];
    float4 sum = make_float4(dsd * self.x, dsd * self.y, dsd * self.z, dsd * self.w);

    int start = g_rowstart[node];
    int deg = g_degi[node];

    for (int j0 = 0; j0 < deg; j0 += 32) {
        int idx = j0 + lane;
        int myid = (idx < deg) ? g_csrc[start + idx] : 0;
        float myds = g_ds[myid];
        int cnt = min(32, deg - j0);
#pragma unroll 4
        for (int k = 0; k < cnt; k++) {
            int s = __shfl_sync(0xffffffffu, myid, k);
            float dss = __shfl_sync(0xffffffffu, myds, k);
            float4 v = hs[(size_t)s * 32 + lane];
            sum.x = fmaf(dss, v.x, sum.x);
            sum.y = fmaf(dss, v.y, sum.y);
            sum.z = fmaf(dss, v.z, sum.z);
            sum.w = fmaf(dss, v.w, sum.w);
        }
    }

    float4 bv = reinterpret_cast<const float4*>(bias)[lane];
    float vx = fmaxf(fmaf(sum.x, dsd, bv.x), 0.0f);
    float vy = fmaxf(fmaf(sum.y, dsd, bv.y), 0.0f);
    float vz = fmaxf(fmaf(sum.z, dsd, bv.z), 0.0f);
    float vw = fmaxf(fmaf(sum.w, dsd, bv.w), 0.0f);

    if (!FINAL) {
        // split into bf16 hi/lo pairs for GEMM2's cp.async staging
        __nv_bfloat16 hx = __float2bfloat16(vx), hy = __float2bfloat16(vy);
        __nv_bfloat16 hz = __float2bfloat16(vz), hw = __float2bfloat16(vw);
        uint32_t hi0 = (uint32_t)__bfloat16_as_ushort(hx) | ((uint32_t)__bfloat16_as_ushort(hy) << 16);
        uint32_t hi1 = (uint32_t)__bfloat16_as_ushort(hz) | ((uint32_t)__bfloat16_as_ushort(hw) << 16);
        uint32_t lo0 = packbf(vx - __bfloat162float(hx), vy - __bfloat162float(hy));
        uint32_t lo1 = packbf(vz - __bfloat162float(hz), vw - __bfloat162float(hw));
        size_t base = (size_t)node * (KPW2 / 2);
        g_aghi[base + lane * 2] = hi0;
        g_aghi[base + lane * 2 + 1] = hi1;
        g_aglo[base + lane * 2] = lo0;
        g_aglo[base + lane * 2 + 1] = lo1;
        if (lane < 8) {             // zero the k-padding 128..143
            g_aghi[base + 64 + lane] = 0u;
            g_aglo[base + 64 + lane] = 0u;
        }
    } else {
        float4* out = reinterpret_cast<float4*>(g_gsum) + batch[node] * 32 + lane;
        asm volatile("red.global.add.v4.f32 [%0], {%1, %2, %3, %4};"
                     :: "l"(out), "f"(vx), "f"(vy), "f"(vz), "f"(vw)
                     : "memory");
    }
}

// ---------------- FC head ----------------
__global__ void __launch_bounds__(64) fc_kernel(const float* __restrict__ Wf1,
                                                const float* __restrict__ bf1,
                                                const float* __restrict__ Wf2,
                                                const float* __restrict__ bf2,
                                                float* __restrict__ out) {
    __shared__ float grow[HID_DIM];
    __shared__ float a[FC_DIM];
    int g = blockIdx.x;
    int t = threadIdx.x;
    float inv = 1.0f / fmaxf(g_gcnt[g], 1.0f);
    grow[t] = g_gsum[g * HID_DIM + t] * inv;
    grow[t + 64] = g_gsum[g * HID_DIM + 64 + t] * inv;
    __syncthreads();
    float acc = bf1[t];
#pragma unroll 8
    for (int k = 0; k < HID_DIM; k++) acc += grow[k] * Wf1[k * FC_DIM + t];
    a[t] = fmaxf(acc, 0.0f);
    __syncthreads();
    if (t < OUT_DIM) {
        float o = bf2[t];
#pragma unroll 8
        for (int j = 0; j < FC_DIM; j++) o += a[j] * Wf2[j * OUT_DIM + t];
        out[g * OUT_DIM + t] = o;
    }
}

// ---------------- fork/join resources ----------------
struct SideStream {
    cudaStream_t s = nullptr;
    cudaEvent_t fork = nullptr, join = nullptr;
    SideStream() {
        if (cudaStreamCreateWithFlags(&s, cudaStreamNonBlocking) != cudaSuccess) { s = nullptr; return; }
        if (cudaEventCreateWithFlags(&fork, cudaEventDisableTiming) != cudaSuccess) { s = nullptr; return; }
        if (cudaEventCreateWithFlags(&join, cudaEventDisableTiming) != cudaSuccess) { s = nullptr; return; }
    }
};
static SideStream& side() { static SideStream ss; return ss; }

// ---------------- launcher ----------------
extern "C" void kernel_launch(void* const* d_in, const int* in_sizes, int n_in,
                              void* d_out, int out_size) {
    const float* x   = (const float*)d_in[0];
    const int* ei    = (const int*)d_in[1];   // [2, E] int32
    const int* batch = (const int*)d_in[2];
    const float* W1  = (const float*)d_in[3];
    const float* b1  = (const float*)d_in[4];
    const float* W2  = (const float*)d_in[5];
    const float* b2  = (const float*)d_in[6];
    const float* Wf1 = (const float*)d_in[7];
    const float* bf1 = (const float*)d_in[8];
    const float* Wf2 = (const float*)d_in[9];
    const float* bf2 = (const float*)d_in[10];
    float* out = (float*)d_out;

    int E = in_sizes[1] / 2;
    int N = in_sizes[2];
    const int* src = ei;
    const int* dst = ei + E;
    int nb = (N_NODES + SCAN_BLK - 1) / SCAN_BLK;

    constexpr int SMEM_DYN = 2 * (2 * 64 * 7 + 2 * 128 * 7) * 16;   // 86016 B
    static bool attr_ok = false;
    if (!attr_ok) {
        cudaFuncSetAttribute(gemm_mma_kernel<5, 30, false>,
                             cudaFuncAttributeMaxDynamicSharedMemorySize, SMEM_DYN);
        cudaFuncSetAttribute(gemm_mma_kernel<3, 18, true>,
                             cudaFuncAttributeMaxDynamicSharedMemorySize, SMEM_DYN);
        attr_ok = true;
    }

    SideStream& ss = side();
    bool forked = (ss.s != nullptr);
    cudaStream_t cs = forked ? ss.s : (cudaStream_t)0;

    if (forked) {
        cudaEventRecord(ss.fork, 0);
        cudaStreamWaitEvent(ss.s, ss.fork, 0);
    }

    // --- CSR build chain (side stream): independent of GEMM1 ---
    zero_kernel<<<(N_NODES + 255) / 256, 256, 0, cs>>>();
    hist_kernel<<<(E + 255) / 256, 256, 0, cs>>>(dst, E);
    scan1_kernel<<<nb, SCAN_BLK, 0, cs>>>();
    scan3_kernel<<<(N_NODES + 255) / 256, 256, 0, cs>>>(nb);
    scatter_kernel<<<(E + 255) / 256, 256, 0, cs>>>(src, dst, E);
    gcnt_kernel<<<1, N_GRAPHS, 0, cs>>>(batch, N);
    if (forked) cudaEventRecord(ss.join, ss.s);

    // --- splits then GEMM1 -> g_h1 ---
    xsplit_kernel<<<((long long)N * (KPW1 / 2) + 255) / 256, 256>>>(x, N);
    wsplit_kernel<false><<<(KPW1 * HID_DIM + 255) / 256, 256>>>(W1);
    wsplit_kernel<true><<<(KPW2 * HID_DIM + 255) / 256, 256>>>(W2);
    gemm_mma_kernel<5, 30, false><<<(N + 63) / 64, 256, SMEM_DYN>>>(N);

    if (forked) cudaStreamWaitEvent(0, ss.join, 0);

    // --- layer-1 aggregation + b1 + relu -> split bf16 ---
    int agg_blocks = (int)(((long long)N * 32 + 255) / 256);
    agg_kernel<false><<<agg_blocks, 256>>>(batch, b1, N);

    // --- GEMM2 -> g_h2 ---
    gemm_mma_kernel<3, 18, true><<<(N + 63) / 64, 256, SMEM_DYN>>>(N);

    // --- layer-2 aggregation + b2 + relu + mean-pool accumulate ---
    agg_kernel<true><<<agg_blocks, 256>>>(batch, b2, N);

    fc_kernel<<<N_GRAPHS, 64>>>(Wf1, bf1, Wf2, bf2, out);
}